// round 11
// baseline (speedup 1.0000x reference)
#include <cuda_runtime.h>
#include <cuda_bf16.h>
#include <cstdint>

#define ULL unsigned long long

static constexpr int Bsz = 2048;
static constexpr int T   = 512;
static constexpr int CH  = 16;
static constexpr int NCH = T / CH;                 // 32
static constexpr int ZPITCH = 68;                  // floats per t-row (bank stagger)
static constexpr int ZBATCH = CH * ZPITCH + 16;    // 1104 floats; 1104 % 32 == 16

// pre-packed Wx fragments (bf16 hi/lo) + bias pairs, built by prep kernel
__device__ uint2  g_Bh[4][8][32];
__device__ uint2  g_Bl[4][8][32];
__device__ float2 g_bias[8][4];

// ---------------- helpers ----------------
__device__ __forceinline__ ULL f2pack(float lo, float hi) {
    ULL r; asm("mov.b64 %0, {%1, %2};" : "=l"(r) : "f"(lo), "f"(hi)); return r;
}
__device__ __forceinline__ void f2unpack(ULL v, float& lo, float& hi) {
    asm("mov.b64 {%0, %1}, %2;" : "=f"(lo), "=f"(hi) : "l"(v));
}
__device__ __forceinline__ ULL ffma2(ULL a, ULL b, ULL c) {
    ULL d; asm("fma.rn.f32x2 %0, %1, %2, %3;" : "=l"(d) : "l"(a), "l"(b), "l"(c)); return d;
}
__device__ __forceinline__ ULL fadd2(ULL a, ULL b) {
    ULL d; asm("add.rn.f32x2 %0, %1, %2;" : "=l"(d) : "l"(a), "l"(b)); return d;
}
__device__ __forceinline__ float fast_sigmoid(float x) {
    float e, r;
    asm("ex2.approx.f32 %0, %1;" : "=f"(e) : "f"(x * -1.4426950408889634f));
    asm("rcp.approx.f32 %0, %1;" : "=f"(r) : "f"(1.0f + e));
    return r;
}
__device__ __forceinline__ uint32_t bf16x2_hi(float x0, float x1) {
    uint32_t r; asm("cvt.rn.bf16x2.f32 %0, %1, %2;" : "=r"(r) : "f"(x1), "f"(x0)); return r;
}
__device__ __forceinline__ uint32_t bf16x2_lo(float x0, float x1, uint32_t hi) {
    float h0 = __uint_as_float(hi << 16);
    float h1 = __uint_as_float(hi & 0xFFFF0000u);
    return bf16x2_hi(x0 - h0, x1 - h1);
}
__device__ __forceinline__ void mma16816(float* c, const uint32_t* a, const uint32_t* b) {
    asm("mma.sync.aligned.m16n8k16.row.col.f32.bf16.bf16.f32 "
        "{%0,%1,%2,%3}, {%4,%5,%6,%7}, {%8,%9}, {%0,%1,%2,%3};"
        : "+f"(c[0]), "+f"(c[1]), "+f"(c[2]), "+f"(c[3])
        : "r"(a[0]), "r"(a[1]), "r"(a[2]), "r"(a[3]), "r"(b[0]), "r"(b[1]));
}

// ============================================================================
// prep: pack Wx into bf16 hi/lo B-fragments (m16n8k16 col-major) + bias pairs
// ============================================================================
__global__ void prep_kernel(const float* __restrict__ Wx, const float* __restrict__ bias) {
    const int tid  = threadIdx.x;
    const int ks   = tid >> 5;
    const int lane = tid & 31;
    const int r    = lane >> 2;
    const int cq   = (lane & 3) * 2;
    const int k0   = ks * 16 + cq;
#pragma unroll
    for (int nt = 0; nt < 8; nt++) {
        const int n = nt * 8 + r;
        float w00 = Wx[(k0)     * 64 + n], w01 = Wx[(k0 + 1) * 64 + n];
        float w10 = Wx[(k0 + 8) * 64 + n], w11 = Wx[(k0 + 9) * 64 + n];
        uint32_t h0 = bf16x2_hi(w00, w01);
        uint32_t h1 = bf16x2_hi(w10, w11);
        g_Bh[ks][nt][lane] = make_uint2(h0, h1);
        g_Bl[ks][nt][lane] = make_uint2(bf16x2_lo(w00, w01, h0), bf16x2_lo(w10, w11, h1));
    }
    if (tid < 32) {
        int nt = tid >> 2, q = tid & 3;
        g_bias[nt][q] = make_float2(bias[nt * 8 + 2 * q], bias[nt * 8 + 2 * q + 1]);
    }
}

// ============================================================================
// Fused LSTM: 2 warps/CTA, 2 batches/warp, lane = one H-unit of one batch.
// Per 16-step chunk, each step also runs 1/16 of next chunk's x*Wx (HMMA)
// into the other zbuf half. No shuffles, no lane predicates on the chain.
// ============================================================================
__global__ void __launch_bounds__(64, 4)
lstm_fused(const float* __restrict__ x,
           const float* __restrict__ Wh,   // [16, 64]
           const float* __restrict__ W2, const float* __restrict__ b2,
           const float* __restrict__ W3, const float* __restrict__ b3,
           const float* __restrict__ Wo, const float* __restrict__ bo,
           float* __restrict__ out)
{
    const int lane = threadIdx.x & 31;
    const int w    = threadIdx.x >> 5;     // 0..1
    const int u    = lane & 15;            // H-unit
    const int breg = lane >> 4;            // batch-within-warp (0/1)
    const int r    = lane >> 2;            // MMA frag row
    const int cq   = (lane & 3) * 2;       // MMA frag col pair
    const int bA   = blockIdx.x * 4 + w * 2;   // first batch of this warp

    __shared__ float zbuf[2][2][2][ZBATCH];          // [warp][buf][batch][..]
    __shared__ __align__(16) float h2[2][2][32];     // dup-pair h state

    // ---- Wh pairs: wif[k] = (Wh[k][u], Wh[k][u+16]); wgo = (g, o) cols ----
    ULL wif[16], wgo[16];
#pragma unroll
    for (int k = 0; k < 16; k++) {
        wif[k] = f2pack(__ldg(&Wh[k * 64 + u]),      __ldg(&Wh[k * 64 + u + 16]));
        wgo[k] = f2pack(__ldg(&Wh[k * 64 + u + 32]), __ldg(&Wh[k * 64 + u + 48]));
    }

    h2[w][breg][2 * u]     = 0.0f;
    h2[w][breg][2 * u + 1] = 0.0f;
    float c_state = 0.0f;
    __syncthreads();

    const float* xbase0 = x + (size_t)(bA)     * T * 64;
    const float* xbase1 = x + (size_t)(bA + 1) * T * 64;

    float2   ar[2][4][4];                 // raw x (chunk-ahead prefetch)
    uint32_t ah[2][4][4], al[2][4][4];    // bf16 frags

    auto load_ar_ks = [&](int b, int ks, int chunk) {
        const float* xb = (b ? xbase1 : xbase0) + (size_t)chunk * CH * 64;
        const int k0 = ks * 16 + cq;
        ar[b][ks][0] = *(const float2*)(xb + (r)     * 64 + k0);
        ar[b][ks][1] = *(const float2*)(xb + (r + 8) * 64 + k0);
        ar[b][ks][2] = *(const float2*)(xb + (r)     * 64 + k0 + 8);
        ar[b][ks][3] = *(const float2*)(xb + (r + 8) * 64 + k0 + 8);
    };
    auto cvt_ks = [&](int b, int ks) {
#pragma unroll
        for (int j = 0; j < 4; j++) {
            ah[b][ks][j] = bf16x2_hi(ar[b][ks][j].x, ar[b][ks][j].y);
            al[b][ks][j] = bf16x2_lo(ar[b][ks][j].x, ar[b][ks][j].y, ah[b][ks][j]);
        }
    };
    // one produce unit: 12 MMAs (3 chains of 4) + bias + 2 STS.64
    auto unit = [&](int s, float* zw) {
        const int b  = s >> 3;
        const int nt = s & 7;
        float chh[4] = {0, 0, 0, 0}, chl[4] = {0, 0, 0, 0}, clh[4] = {0, 0, 0, 0};
#pragma unroll
        for (int ks = 0; ks < 4; ks++) {
            uint2 bh = __ldg(&g_Bh[ks][nt][lane]);
            uint2 bl = __ldg(&g_Bl[ks][nt][lane]);
            mma16816(chh, ah[b][ks], &bh.x);
            mma16816(chl, ah[b][ks], &bl.x);
            mma16816(clh, al[b][ks], &bh.x);
        }
        float2 bs = __ldg(&g_bias[nt][cq >> 1]);
        float* zd = zw + b * ZBATCH;
        *(float2*)(zd + (r)     * ZPITCH + nt * 8 + cq) =
            make_float2(chh[0] + chl[0] + clh[0] + bs.x, chh[1] + chl[1] + clh[1] + bs.y);
        *(float2*)(zd + (r + 8) * ZPITCH + nt * 8 + cq) =
            make_float2(chh[2] + chl[2] + clh[2] + bs.x, chh[3] + chl[3] + clh[3] + bs.y);
    };

    // ---- prologue: produce chunk 0 into buf 0; prefetch x(chunk 1) ----
#pragma unroll
    for (int b = 0; b < 2; b++)
#pragma unroll
        for (int ks = 0; ks < 4; ks++) load_ar_ks(b, ks, 0);
#pragma unroll
    for (int b = 0; b < 2; b++)
#pragma unroll
        for (int ks = 0; ks < 4; ks++) cvt_ks(b, ks);
#pragma unroll
    for (int s = 0; s < 16; s++) unit(s, &zbuf[w][0][0][0]);
#pragma unroll
    for (int b = 0; b < 2; b++)
#pragma unroll
        for (int ks = 0; ks < 4; ks++) load_ar_ks(b, ks, 1);
    __syncwarp();

    float*       h2L     = &h2[w][breg][0];
    ULL*         h2store = (ULL*)&h2[w][breg][2 * u];
    const ulonglong2* h2v = (const ulonglong2*)h2L;

#pragma unroll 1
    for (int ch = 0; ch < NCH; ch++) {
        const int   pb      = ch & 1;
        float*      zw_next = &zbuf[w][pb ^ 1][0][0];
        const float* zL     = &zbuf[w][pb][0][0] + breg * ZBATCH + u;
        const bool  more    = (ch + 1 < NCH);
        const int   chL     = (ch + 2 < NCH) ? (ch + 2) : (NCH - 1);

        if (more) {             // frags for next chunk's batch-A units (steps 0-7)
#pragma unroll
            for (int ks = 0; ks < 4; ks++) cvt_ks(0, ks);
        }
        float zi = zL[0], zf = zL[16], zg = zL[32], zo = zL[48];

#pragma unroll
        for (int tl = 0; tl < CH; tl++) {
            // h dup-pairs: 8x LDS.128 (broadcast per half-warp)
            ULL hd[16];
#pragma unroll
            for (int j = 0; j < 8; j++) {
                ulonglong2 v = h2v[j];
                hd[2 * j] = v.x; hd[2 * j + 1] = v.y;
            }

            ULL if0 = f2pack(zi, zf), if1 = 0ULL;
            ULL go0 = f2pack(zg, zo), go1 = 0ULL;
#pragma unroll
            for (int k = 0; k < 16; k++) {
                if (k & 1) { if1 = ffma2(hd[k], wif[k], if1); go1 = ffma2(hd[k], wgo[k], go1); }
                else       { if0 = ffma2(hd[k], wif[k], if0); go0 = ffma2(hd[k], wgo[k], go0); }
            }
            float zI, zF, zG, zO;
            f2unpack(fadd2(if0, if1), zI, zF);
            f2unpack(fadd2(go0, go1), zG, zO);

            float gi = fast_sigmoid(zI);
            float gf = fast_sigmoid(zF);
            float gg = fmaxf(zG, 0.0f);
            float go = fast_sigmoid(zO);

            c_state = gf * c_state + gi * gg;
            float h = go * fmaxf(c_state, 0.0f);
            *h2store = f2pack(h, h);

            // ---- interleaved produce of next chunk ----
            if (more) {
                unit(tl, zw_next);
                if (tl == 2) { cvt_ks(1, 0); cvt_ks(1, 1); }   // batch-B frags
                if (tl == 3) { cvt_ks(1, 2); cvt_ks(1, 3); }
            }
            if (tl >= 4 && tl < 8) load_ar_ks(0, tl - 4, chL);   // x prefetch (ch+2)
            if (tl >= 12)          load_ar_ks(1, tl - 12, chL);

            __syncwarp();
            if (tl + 1 < CH) {
                zi = zL[(tl + 1) * ZPITCH];
                zf = zL[(tl + 1) * ZPITCH + 16];
                zg = zL[(tl + 1) * ZPITCH + 32];
                zo = zL[(tl + 1) * ZPITCH + 48];
            }
        }
    }

    // ---- MLP head: lanes 0 and 16 (one per batch) ----
    if (u == 0) {
        const int batch = bA + breg;
        float hT[16];
#pragma unroll
        for (int j = 0; j < 16; j++) hT[j] = h2L[2 * j];
        float x2v[8];
#pragma unroll
        for (int uu = 0; uu < 8; uu++) {
            float s = __ldg(&b2[uu]);
#pragma unroll
            for (int j = 0; j < 16; j++) s += hT[j] * __ldg(&W2[j * 8 + uu]);
            x2v[uu] = fmaxf(s, 0.0f);
        }
        float x3v[4];
#pragma unroll
        for (int uu = 0; uu < 4; uu++) {
            float s = __ldg(&b3[uu]);
#pragma unroll
            for (int j = 0; j < 8; j++) s += x2v[j] * __ldg(&W3[j * 4 + uu]);
            x3v[uu] = fmaxf(s, 0.0f);
        }
        float s = __ldg(&bo[0]);
#pragma unroll
        for (int uu = 0; uu < 4; uu++) s += x3v[uu] * __ldg(&Wo[uu]);
        out[batch] = fast_sigmoid(s);
    }
}

extern "C" void kernel_launch(void* const* d_in, const int* in_sizes, int n_in,
                              void* d_out, int out_size) {
    (void)in_sizes; (void)n_in; (void)out_size;
    const float* x  = (const float*)d_in[0];
    const float* Wx = (const float*)d_in[1];
    const float* Wh = (const float*)d_in[2];
    const float* b  = (const float*)d_in[3];
    const float* W2 = (const float*)d_in[4];
    const float* b2 = (const float*)d_in[5];
    const float* W3 = (const float*)d_in[6];
    const float* b3 = (const float*)d_in[7];
    const float* Wo = (const float*)d_in[8];
    const float* bo = (const float*)d_in[9];
    float* out = (float*)d_out;

    prep_kernel<<<1, 128>>>(Wx, b);
    lstm_fused<<<Bsz / 4, 64>>>(x, Wh, W2, b2, W3, b3, Wo, bo, out);
}

// round 12
// speedup vs baseline: 1.0641x; 1.0641x over previous
#include <cuda_runtime.h>
#include <cuda_bf16.h>
#include <cstdint>

#define ULL unsigned long long

static constexpr int Bsz = 2048;
static constexpr int T   = 512;
static constexpr int CH  = 16;
static constexpr int NCH = T / CH;     // 32
static constexpr int ZP  = 68;         // zbuf pitch (floats)

// pre-packed Wx fragments (bf16 hi/lo) + bias pairs (built by prep kernel)
__device__ uint2  g_Bh[4][8][32];
__device__ uint2  g_Bl[4][8][32];
__device__ float2 g_bias[8][4];

// ---------------- helpers ----------------
__device__ __forceinline__ ULL f2pack(float lo, float hi) {
    ULL r; asm("mov.b64 %0, {%1, %2};" : "=l"(r) : "f"(lo), "f"(hi)); return r;
}
__device__ __forceinline__ void f2unpack(ULL v, float& lo, float& hi) {
    asm("mov.b64 {%0, %1}, %2;" : "=f"(lo), "=f"(hi) : "l"(v));
}
__device__ __forceinline__ ULL ffma2(ULL a, ULL b, ULL c) {
    ULL d; asm("fma.rn.f32x2 %0, %1, %2, %3;" : "=l"(d) : "l"(a), "l"(b), "l"(c)); return d;
}
__device__ __forceinline__ ULL fadd2(ULL a, ULL b) {
    ULL d; asm("add.rn.f32x2 %0, %1, %2;" : "=l"(d) : "l"(a), "l"(b)); return d;
}
__device__ __forceinline__ float fast_sigmoid(float x) {
    float e, r;
    asm("ex2.approx.f32 %0, %1;" : "=f"(e) : "f"(x * -1.4426950408889634f));
    asm("rcp.approx.f32 %0, %1;" : "=f"(r) : "f"(1.0f + e));
    return r;
}
__device__ __forceinline__ uint32_t bf16x2_hi(float x0, float x1) {
    uint32_t r; asm("cvt.rn.bf16x2.f32 %0, %1, %2;" : "=r"(r) : "f"(x1), "f"(x0)); return r;
}
__device__ __forceinline__ uint32_t bf16x2_lo(float x0, float x1, uint32_t hi) {
    float h0 = __uint_as_float(hi << 16);
    float h1 = __uint_as_float(hi & 0xFFFF0000u);
    return bf16x2_hi(x0 - h0, x1 - h1);
}
__device__ __forceinline__ void mma16816(float* c, const uint32_t* a, const uint32_t* b) {
    asm("mma.sync.aligned.m16n8k16.row.col.f32.bf16.bf16.f32 "
        "{%0,%1,%2,%3}, {%4,%5,%6,%7}, {%8,%9}, {%0,%1,%2,%3};"
        : "+f"(c[0]), "+f"(c[1]), "+f"(c[2]), "+f"(c[3])
        : "r"(a[0]), "r"(a[1]), "r"(a[2]), "r"(a[3]), "r"(b[0]), "r"(b[1]));
}

// ============================================================================
// prep: pack Wx into bf16 hi/lo B-fragments (m16n8k16 col-major) + bias pairs
// ============================================================================
__global__ void prep_kernel(const float* __restrict__ Wx, const float* __restrict__ bias) {
    const int tid  = threadIdx.x;
    const int ks   = tid >> 5;
    const int lane = tid & 31;
    const int r    = lane >> 2;
    const int cq   = (lane & 3) * 2;
    const int k0   = ks * 16 + cq;
#pragma unroll
    for (int nt = 0; nt < 8; nt++) {
        const int n = nt * 8 + r;
        float w00 = Wx[(k0)     * 64 + n], w01 = Wx[(k0 + 1) * 64 + n];
        float w10 = Wx[(k0 + 8) * 64 + n], w11 = Wx[(k0 + 9) * 64 + n];
        uint32_t h0 = bf16x2_hi(w00, w01);
        uint32_t h1 = bf16x2_hi(w10, w11);
        g_Bh[ks][nt][lane] = make_uint2(h0, h1);
        g_Bl[ks][nt][lane] = make_uint2(bf16x2_lo(w00, w01, h0), bf16x2_lo(w10, w11, h1));
    }
    if (tid < 32) {
        int nt = tid >> 2, q = tid & 3;
        g_bias[nt][q] = make_float2(bias[nt * 8 + 2 * q], bias[nt * 8 + 2 * q + 1]);
    }
}

// ============================================================================
// Fused LSTM, R10 layout (1 warp = 1 batch, 4 warps/CTA) with the next
// chunk's x*Wx produce interleaved INTO the 16 consume steps:
//   steps 0-3 : cvt x -> bf16 frags (chunk ch+1)
//   steps 4-11: one MMA unit each (8 n-tiles) -> zbuf[other]
//   steps 12-15: LDG x (chunk ch+2)
// ============================================================================
__global__ void __launch_bounds__(128, 4)
lstm_fused(const float* __restrict__ x,
           const float* __restrict__ Wh,   // [16, 64]
           const float* __restrict__ W2, const float* __restrict__ b2,
           const float* __restrict__ W3, const float* __restrict__ b3,
           const float* __restrict__ Wo, const float* __restrict__ bo,
           float* __restrict__ out)
{
    const int lane = threadIdx.x & 31;
    const int w    = threadIdx.x >> 5;
    const int batch = blockIdx.x * 4 + w;
    const int r  = lane >> 2;          // 0..7
    const int cq = (lane & 3) * 2;     // 0,2,4,6

    __shared__ float zbuf[4][2][CH][ZP];             // double-buffered z chunk
    __shared__ __align__(16) float sh[4][32];        // h state (16 used)

    // ---- Wh weight pairs in registers (cols lane, lane+32) ----
    ULL wha[8], whb[8];
#pragma unroll
    for (int kk = 0; kk < 8; kk++) {
        wha[kk] = f2pack(__ldg(&Wh[(2 * kk) * 64 + lane]),
                         __ldg(&Wh[(2 * kk + 1) * 64 + lane]));
        whb[kk] = f2pack(__ldg(&Wh[(2 * kk) * 64 + lane + 32]),
                         __ldg(&Wh[(2 * kk + 1) * 64 + lane + 32]));
    }

    sh[w][lane] = 0.0f;
    float c_state = 0.0f;
    __syncthreads();

    const float* xb = x + (size_t)batch * T * 64;

    float2   ar[4][4];                 // raw x (live steps 12..3 of next chunk)
    uint32_t ah[4][4], al[4][4];       // bf16 frags (live steps 3..11)

    auto load_ks = [&](int ks, int chunk) {
        const float* xc = xb + (size_t)chunk * CH * 64;
        const int k0 = ks * 16 + cq;
        ar[ks][0] = *(const float2*)(xc + (r)     * 64 + k0);
        ar[ks][1] = *(const float2*)(xc + (r + 8) * 64 + k0);
        ar[ks][2] = *(const float2*)(xc + (r)     * 64 + k0 + 8);
        ar[ks][3] = *(const float2*)(xc + (r + 8) * 64 + k0 + 8);
    };
    auto cvt_ks = [&](int ks) {
#pragma unroll
        for (int j = 0; j < 4; j++) {
            ah[ks][j] = bf16x2_hi(ar[ks][j].x, ar[ks][j].y);
            al[ks][j] = bf16x2_lo(ar[ks][j].x, ar[ks][j].y, ah[ks][j]);
        }
    };
    // one produce unit (n-tile nt): 12 MMAs in 3 independent 4-chains + 2 STS
    auto unit = [&](int nt, float* zd) {
        float chh[4] = {0, 0, 0, 0}, chl[4] = {0, 0, 0, 0}, clh[4] = {0, 0, 0, 0};
#pragma unroll
        for (int ks = 0; ks < 4; ks++) {
            uint2 bh = __ldg(&g_Bh[ks][nt][lane]);
            uint2 bl = __ldg(&g_Bl[ks][nt][lane]);
            mma16816(chh, ah[ks], &bh.x);
            mma16816(chl, ah[ks], &bl.x);
            mma16816(clh, al[ks], &bh.x);
        }
        float2 bs = __ldg(&g_bias[nt][cq >> 1]);
        *(float2*)(zd + (r)     * ZP + nt * 8 + cq) =
            make_float2(chh[0] + chl[0] + clh[0] + bs.x, chh[1] + chl[1] + clh[1] + bs.y);
        *(float2*)(zd + (r + 8) * ZP + nt * 8 + cq) =
            make_float2(chh[2] + chl[2] + clh[2] + bs.x, chh[3] + chl[3] + clh[3] + bs.y);
    };

    // ---- prologue: chunk 0 produced serially; ar <- x(chunk 1) ----
#pragma unroll
    for (int ks = 0; ks < 4; ks++) load_ks(ks, 0);
#pragma unroll
    for (int ks = 0; ks < 4; ks++) cvt_ks(ks);
#pragma unroll
    for (int nt = 0; nt < 8; nt++) unit(nt, &zbuf[w][0][0][0]);
#pragma unroll
    for (int ks = 0; ks < 4; ks++) load_ks(ks, 1);
    __syncwarp();

    const ulonglong2* hv = (const ulonglong2*)sh[w];

#pragma unroll 1
    for (int ch = 0; ch < NCH; ch++) {
        const int    pb   = ch & 1;
        float*       znx  = &zbuf[w][pb ^ 1][0][0];
        const float (*zc)[ZP] = zbuf[w][pb];
        const bool   more = (ch + 1 < NCH);   // produce chunk ch+1 this pass
        const bool   ld2  = (ch + 2 < NCH);   // load x for chunk ch+2

        float zA = zc[0][lane];
        float zB = zc[0][lane + 32];

#pragma unroll
        for (int tl = 0; tl < CH; tl++) {
            // ---- consume step tl (identical numerics to R10) ----
            ULL hp[8];
            {
                ulonglong2 v0 = hv[0], v1 = hv[1], v2 = hv[2], v3 = hv[3];
                hp[0] = v0.x; hp[1] = v0.y; hp[2] = v1.x; hp[3] = v1.y;
                hp[4] = v2.x; hp[5] = v2.y; hp[6] = v3.x; hp[7] = v3.y;
            }
            float zAn = 0.0f, zBn = 0.0f;
            if (tl + 1 < CH) {
                zAn = zc[tl + 1][lane];
                zBn = zc[tl + 1][lane + 32];
            }

            ULL aa0 = f2pack(zA, 0.0f), aa1 = 0ULL;
            ULL ab0 = f2pack(zB, 0.0f), ab1 = 0ULL;
#pragma unroll
            for (int k = 0; k < 8; k++) {
                if (k & 1) { aa1 = ffma2(hp[k], wha[k], aa1); ab1 = ffma2(hp[k], whb[k], ab1); }
                else       { aa0 = ffma2(hp[k], wha[k], aa0); ab0 = ffma2(hp[k], whb[k], ab0); }
            }
            ULL sa = fadd2(aa0, aa1), sb = fadd2(ab0, ab1);
            float a0, a1, b0, b1;
            f2unpack(sa, a0, a1);
            f2unpack(sb, b0, b1);
            float za  = a0 + a1;   // lane<16: i | lane>=16: f
            float zbv = b0 + b1;   // lane<16: g | lane>=16: o

            float v1 = fast_sigmoid(za);
            float v2 = (lane < 16) ? fmaxf(zbv, 0.0f) : fast_sigmoid(zbv);

            float fpart = __shfl_xor_sync(0xFFFFFFFFu, v1, 16);
            float opart = __shfl_xor_sync(0xFFFFFFFFu, v2, 16);

            c_state = fpart * c_state + v1 * v2;          // valid lanes 0..15
            float hnew = opart * fmaxf(c_state, 0.0f);
            sh[w][lane] = hnew;                           // branchless store

            // ---- interleaved produce / cvt / prefetch ----
            if (more) {
                if (tl < 4)                 cvt_ks(tl);          // frags for ch+1
                else if (tl < 12)           unit(tl - 4, znx);   // z(ch+1) tiles
            }
            if (ld2 && tl >= 12)            load_ks(tl - 12, ch + 2);

            __syncwarp();
            zA = zAn; zB = zBn;
        }
    }

    // ---- MLP head: lane 0 per warp ----
    if (lane == 0) {
        const float* hT = sh[w];
        float x2v[8];
#pragma unroll
        for (int u = 0; u < 8; u++) {
            float s = __ldg(&b2[u]);
#pragma unroll
            for (int j = 0; j < 16; j++) s += hT[j] * __ldg(&W2[j * 8 + u]);
            x2v[u] = fmaxf(s, 0.0f);
        }
        float x3v[4];
#pragma unroll
        for (int u = 0; u < 4; u++) {
            float s = __ldg(&b3[u]);
#pragma unroll
            for (int j = 0; j < 8; j++) s += x2v[j] * __ldg(&W3[j * 4 + u]);
            x3v[u] = fmaxf(s, 0.0f);
        }
        float s = __ldg(&bo[0]);
#pragma unroll
        for (int u = 0; u < 4; u++) s += x3v[u] * __ldg(&Wo[u]);
        out[batch] = fast_sigmoid(s);
    }
}

extern "C" void kernel_launch(void* const* d_in, const int* in_sizes, int n_in,
                              void* d_out, int out_size) {
    (void)in_sizes; (void)n_in; (void)out_size;
    const float* x  = (const float*)d_in[0];
    const float* Wx = (const float*)d_in[1];
    const float* Wh = (const float*)d_in[2];
    const float* b  = (const float*)d_in[3];
    const float* W2 = (const float*)d_in[4];
    const float* b2 = (const float*)d_in[5];
    const float* W3 = (const float*)d_in[6];
    const float* b3 = (const float*)d_in[7];
    const float* Wo = (const float*)d_in[8];
    const float* bo = (const float*)d_in[9];
    float* out = (float*)d_out;

    prep_kernel<<<1, 128>>>(Wx, b);
    lstm_fused<<<Bsz / 4, 128>>>(x, Wh, W2, b2, W3, b3, Wo, bo, out);
}

// round 13
// speedup vs baseline: 1.0725x; 1.0079x over previous
#include <cuda_runtime.h>
#include <cuda_bf16.h>
#include <cstdint>

#define ULL unsigned long long

static constexpr int Bsz = 2048;
static constexpr int T   = 512;
static constexpr int CH  = 16;
static constexpr int NCH = T / CH;     // 32
static constexpr int ZP  = 68;         // zbuf pitch (floats)

// pre-packed Wx fragments (bf16 hi/lo) + bias pairs (built by prep kernel)
__device__ uint2  g_Bh[4][8][32];
__device__ uint2  g_Bl[4][8][32];
__device__ float2 g_bias[8][4];

// ---------------- helpers ----------------
__device__ __forceinline__ ULL f2pack(float lo, float hi) {
    ULL r; asm("mov.b64 %0, {%1, %2};" : "=l"(r) : "f"(lo), "f"(hi)); return r;
}
__device__ __forceinline__ void f2unpack(ULL v, float& lo, float& hi) {
    asm("mov.b64 {%0, %1}, %2;" : "=f"(lo), "=f"(hi) : "l"(v));
}
__device__ __forceinline__ ULL ffma2(ULL a, ULL b, ULL c) {
    ULL d; asm("fma.rn.f32x2 %0, %1, %2, %3;" : "=l"(d) : "l"(a), "l"(b), "l"(c)); return d;
}
__device__ __forceinline__ ULL fadd2(ULL a, ULL b) {
    ULL d; asm("add.rn.f32x2 %0, %1, %2;" : "=l"(d) : "l"(a), "l"(b)); return d;
}
__device__ __forceinline__ float fast_sigmoid(float x) {
    float e, r;
    asm("ex2.approx.f32 %0, %1;" : "=f"(e) : "f"(x * -1.4426950408889634f));
    asm("rcp.approx.f32 %0, %1;" : "=f"(r) : "f"(1.0f + e));
    return r;
}
__device__ __forceinline__ uint32_t bf16x2_hi(float x0, float x1) {
    uint32_t r; asm("cvt.rn.bf16x2.f32 %0, %1, %2;" : "=r"(r) : "f"(x1), "f"(x0)); return r;
}
__device__ __forceinline__ uint32_t bf16x2_lo(float x0, float x1, uint32_t hi) {
    float h0 = __uint_as_float(hi << 16);
    float h1 = __uint_as_float(hi & 0xFFFF0000u);
    return bf16x2_hi(x0 - h0, x1 - h1);
}
__device__ __forceinline__ void mma16816(float* c, const uint32_t* a, const uint32_t* b) {
    asm("mma.sync.aligned.m16n8k16.row.col.f32.bf16.bf16.f32 "
        "{%0,%1,%2,%3}, {%4,%5,%6,%7}, {%8,%9}, {%0,%1,%2,%3};"
        : "+f"(c[0]), "+f"(c[1]), "+f"(c[2]), "+f"(c[3])
        : "r"(a[0]), "r"(a[1]), "r"(a[2]), "r"(a[3]), "r"(b[0]), "r"(b[1]));
}

// ============================================================================
// prep: pack Wx into bf16 hi/lo B-fragments (m16n8k16 col-major) + bias pairs
// ============================================================================
__global__ void prep_kernel(const float* __restrict__ Wx, const float* __restrict__ bias) {
    const int tid  = threadIdx.x;
    const int ks   = tid >> 5;
    const int lane = tid & 31;
    const int r    = lane >> 2;
    const int cq   = (lane & 3) * 2;
    const int k0   = ks * 16 + cq;
#pragma unroll
    for (int nt = 0; nt < 8; nt++) {
        const int n = nt * 8 + r;
        float w00 = Wx[(k0)     * 64 + n], w01 = Wx[(k0 + 1) * 64 + n];
        float w10 = Wx[(k0 + 8) * 64 + n], w11 = Wx[(k0 + 9) * 64 + n];
        uint32_t h0 = bf16x2_hi(w00, w01);
        uint32_t h1 = bf16x2_hi(w10, w11);
        g_Bh[ks][nt][lane] = make_uint2(h0, h1);
        g_Bl[ks][nt][lane] = make_uint2(bf16x2_lo(w00, w01, h0), bf16x2_lo(w10, w11, h1));
    }
    if (tid < 32) {
        int nt = tid >> 2, q = tid & 3;
        g_bias[nt][q] = make_float2(bias[nt * 8 + 2 * q], bias[nt * 8 + 2 * q + 1]);
    }
}

// ============================================================================
// Fused LSTM, R10 layout (1 warp = 1 batch, 4 warps/CTA). Next chunk's x*Wx
// produce interleaved into the 16 consume steps, with the per-step
// __syncwarp() placed IMMEDIATELY after the h store so produce work issues
// outside the fenced h-store->h-load window (fills stall slots).
// ============================================================================
__global__ void __launch_bounds__(128, 4)
lstm_fused(const float* __restrict__ x,
           const float* __restrict__ Wh,   // [16, 64]
           const float* __restrict__ W2, const float* __restrict__ b2,
           const float* __restrict__ W3, const float* __restrict__ b3,
           const float* __restrict__ Wo, const float* __restrict__ bo,
           float* __restrict__ out)
{
    const int lane = threadIdx.x & 31;
    const int w    = threadIdx.x >> 5;
    const int batch = blockIdx.x * 4 + w;
    const int r  = lane >> 2;          // 0..7
    const int cq = (lane & 3) * 2;     // 0,2,4,6

    __shared__ float zbuf[4][2][CH][ZP];             // double-buffered z chunk
    __shared__ __align__(16) float sh[4][32];        // h state (16 used)

    // ---- Wh weight pairs in registers (cols lane, lane+32) ----
    ULL wha[8], whb[8];
#pragma unroll
    for (int kk = 0; kk < 8; kk++) {
        wha[kk] = f2pack(__ldg(&Wh[(2 * kk) * 64 + lane]),
                         __ldg(&Wh[(2 * kk + 1) * 64 + lane]));
        whb[kk] = f2pack(__ldg(&Wh[(2 * kk) * 64 + lane + 32]),
                         __ldg(&Wh[(2 * kk + 1) * 64 + lane + 32]));
    }

    sh[w][lane] = 0.0f;
    float c_state = 0.0f;
    __syncthreads();

    const float* xb = x + (size_t)batch * T * 64;

    float2   ar[4][4];                 // raw x (live steps 12..3 of next chunk)
    uint32_t ah[4][4], al[4][4];       // bf16 frags (live steps 3..11)

    auto load_ks = [&](int ks, int chunk) {
        const float* xc = xb + (size_t)chunk * CH * 64;
        const int k0 = ks * 16 + cq;
        ar[ks][0] = *(const float2*)(xc + (r)     * 64 + k0);
        ar[ks][1] = *(const float2*)(xc + (r + 8) * 64 + k0);
        ar[ks][2] = *(const float2*)(xc + (r)     * 64 + k0 + 8);
        ar[ks][3] = *(const float2*)(xc + (r + 8) * 64 + k0 + 8);
    };
    auto cvt_ks = [&](int ks) {
#pragma unroll
        for (int j = 0; j < 4; j++) {
            ah[ks][j] = bf16x2_hi(ar[ks][j].x, ar[ks][j].y);
            al[ks][j] = bf16x2_lo(ar[ks][j].x, ar[ks][j].y, ah[ks][j]);
        }
    };
    // one produce unit (n-tile nt): 12 MMAs in 3 independent 4-chains + 2 STS
    auto unit = [&](int nt, float* zd) {
        float chh[4] = {0, 0, 0, 0}, chl[4] = {0, 0, 0, 0}, clh[4] = {0, 0, 0, 0};
#pragma unroll
        for (int ks = 0; ks < 4; ks++) {
            uint2 bh = __ldg(&g_Bh[ks][nt][lane]);
            uint2 bl = __ldg(&g_Bl[ks][nt][lane]);
            mma16816(chh, ah[ks], &bh.x);
            mma16816(chl, ah[ks], &bl.x);
            mma16816(clh, al[ks], &bh.x);
        }
        float2 bs = __ldg(&g_bias[nt][cq >> 1]);
        *(float2*)(zd + (r)     * ZP + nt * 8 + cq) =
            make_float2(chh[0] + chl[0] + clh[0] + bs.x, chh[1] + chl[1] + clh[1] + bs.y);
        *(float2*)(zd + (r + 8) * ZP + nt * 8 + cq) =
            make_float2(chh[2] + chl[2] + clh[2] + bs.x, chh[3] + chl[3] + clh[3] + bs.y);
    };

    // ---- prologue: chunk 0 produced serially; ar <- x(chunk 1) ----
#pragma unroll
    for (int ks = 0; ks < 4; ks++) load_ks(ks, 0);
#pragma unroll
    for (int ks = 0; ks < 4; ks++) cvt_ks(ks);
#pragma unroll
    for (int nt = 0; nt < 8; nt++) unit(nt, &zbuf[w][0][0][0]);
#pragma unroll
    for (int ks = 0; ks < 4; ks++) load_ks(ks, 1);
    __syncwarp();

    const ulonglong2* hv = (const ulonglong2*)sh[w];

#pragma unroll 1
    for (int ch = 0; ch < NCH; ch++) {
        const int    pb   = ch & 1;
        float*       znx  = &zbuf[w][pb ^ 1][0][0];
        const float (*zc)[ZP] = zbuf[w][pb];
        const bool   more = (ch + 1 < NCH);   // produce chunk ch+1 this pass
        const bool   ld2  = (ch + 2 < NCH);   // load x for chunk ch+2

        float zA = zc[0][lane];
        float zB = zc[0][lane + 32];

#pragma unroll
        for (int tl = 0; tl < CH; tl++) {
            // ---- consume step tl (identical numerics to R10) ----
            ULL hp[8];
            {
                ulonglong2 v0 = hv[0], v1 = hv[1], v2 = hv[2], v3 = hv[3];
                hp[0] = v0.x; hp[1] = v0.y; hp[2] = v1.x; hp[3] = v1.y;
                hp[4] = v2.x; hp[5] = v2.y; hp[6] = v3.x; hp[7] = v3.y;
            }
            float zAn = 0.0f, zBn = 0.0f;
            if (tl + 1 < CH) {                 // compile-time (unrolled)
                zAn = zc[tl + 1][lane];
                zBn = zc[tl + 1][lane + 32];
            }

            ULL aa0 = f2pack(zA, 0.0f), aa1 = 0ULL;
            ULL ab0 = f2pack(zB, 0.0f), ab1 = 0ULL;
#pragma unroll
            for (int k = 0; k < 8; k++) {
                if (k & 1) { aa1 = ffma2(hp[k], wha[k], aa1); ab1 = ffma2(hp[k], whb[k], ab1); }
                else       { aa0 = ffma2(hp[k], wha[k], aa0); ab0 = ffma2(hp[k], whb[k], ab0); }
            }
            ULL sa = fadd2(aa0, aa1), sb = fadd2(ab0, ab1);
            float a0, a1, b0, b1;
            f2unpack(sa, a0, a1);
            f2unpack(sb, b0, b1);
            float za  = a0 + a1;   // lane<16: i | lane>=16: f
            float zbv = b0 + b1;   // lane<16: g | lane>=16: o

            float v1 = fast_sigmoid(za);
            float v2 = (lane < 16) ? fmaxf(zbv, 0.0f) : fast_sigmoid(zbv);

            float fpart = __shfl_xor_sync(0xFFFFFFFFu, v1, 16);
            float opart = __shfl_xor_sync(0xFFFFFFFFu, v2, 16);

            c_state = fpart * c_state + v1 * v2;          // valid lanes 0..15
            float hnew = opart * fmaxf(c_state, 0.0f);
            sh[w][lane] = hnew;                           // branchless store
            __syncwarp();   // ONLY fences h-store -> next h-load; produce below
                            // issues outside the fenced window and overlaps
                            // the next step's LDS/gate chain.

            // ---- interleaved produce / cvt / prefetch (unfenced) ----
            if (more) {
                if (tl < 4)                 cvt_ks(tl);          // frags for ch+1
                else if (tl < 12)           unit(tl - 4, znx);   // z(ch+1) tiles
            }
            if (ld2 && tl >= 12)            load_ks(tl - 12, ch + 2);

            zA = zAn; zB = zBn;
        }
        __syncwarp();   // chunk boundary: last produce STS visible before
                        // next chunk's z reads from that buffer.
    }

    // ---- MLP head: lane 0 per warp ----
    if (lane == 0) {
        const float* hT = sh[w];
        float x2v[8];
#pragma unroll
        for (int u = 0; u < 8; u++) {
            float s = __ldg(&b2[u]);
#pragma unroll
            for (int j = 0; j < 16; j++) s += hT[j] * __ldg(&W2[j * 8 + u]);
            x2v[u] = fmaxf(s, 0.0f);
        }
        float x3v[4];
#pragma unroll
        for (int u = 0; u < 4; u++) {
            float s = __ldg(&b3[u]);
#pragma unroll
            for (int j = 0; j < 8; j++) s += x2v[j] * __ldg(&W3[j * 4 + u]);
            x3v[u] = fmaxf(s, 0.0f);
        }
        float s = __ldg(&bo[0]);
#pragma unroll
        for (int u = 0; u < 4; u++) s += x3v[u] * __ldg(&Wo[u]);
        out[batch] = fast_sigmoid(s);
    }
}

extern "C" void kernel_launch(void* const* d_in, const int* in_sizes, int n_in,
                              void* d_out, int out_size) {
    (void)in_sizes; (void)n_in; (void)out_size;
    const float* x  = (const float*)d_in[0];
    const float* Wx = (const float*)d_in[1];
    const float* Wh = (const float*)d_in[2];
    const float* b  = (const float*)d_in[3];
    const float* W2 = (const float*)d_in[4];
    const float* b2 = (const float*)d_in[5];
    const float* W3 = (const float*)d_in[6];
    const float* b3 = (const float*)d_in[7];
    const float* Wo = (const float*)d_in[8];
    const float* bo = (const float*)d_in[9];
    float* out = (float*)d_out;

    prep_kernel<<<1, 128>>>(Wx, b);
    lstm_fused<<<Bsz / 4, 128>>>(x, Wh, W2, b2, W3, b3, Wo, bo, out);
}